// round 3
// baseline (speedup 1.0000x reference)
#include <cuda_runtime.h>

#define TOK   16384
#define KCB   8192
#define CDIM  256
#define BM    64          // tokens per block
#define BNT   128         // codes per k-tile
#define BKT   16          // channels per smem stage

#define ZS_S  68          // zs[c][t] stride (floats), 16B-aligned rows
#define CB_S  132         // cbs[c][k] stride (floats), 16B-aligned rows
#define SMEM_FLOATS (CDIM * ZS_S + 2 * BKT * CB_S)
#define SMEM_BYTES  (SMEM_FLOATS * 4)

// scratch (device globals: no allocation allowed)
__device__ float g_zflat[TOK * CDIM];
__device__ float g_zsq[TOK];
__device__ float g_esq[KCB];
__device__ int   g_codes[TOK];
__device__ float g_tokloss[TOK];

// ---------------------------------------------------------------------------
// packed f32x2 helpers
// ---------------------------------------------------------------------------
__device__ __forceinline__ unsigned long long splat2(float x) {
    unsigned long long r;
    asm("mov.b64 %0, {%1, %1};" : "=l"(r) : "r"(__float_as_uint(x)));
    return r;
}
__device__ __forceinline__ void fma2(unsigned long long& d,
                                     unsigned long long a,
                                     unsigned long long b) {
    asm("fma.rn.f32x2 %0, %1, %2, %0;" : "+l"(d) : "l"(a), "l"(b));
}
__device__ __forceinline__ void unpack2(unsigned long long v, float& lo, float& hi) {
    unsigned int l, h;
    asm("mov.b64 {%0, %1}, %2;" : "=r"(l), "=r"(h) : "l"(v));
    lo = __uint_as_float(l);
    hi = __uint_as_float(h);
}

// ---------------------------------------------------------------------------
// 1) transpose z (B,C,H,W) -> z_flat (t, c)
// ---------------------------------------------------------------------------
__global__ void k_transpose(const float* __restrict__ z) {
    __shared__ float tile[32][33];
    int b  = blockIdx.z;
    int c0 = blockIdx.y << 5;
    int p0 = blockIdx.x << 5;
    int tx = threadIdx.x, ty = threadIdx.y;
    tile[ty][tx] = z[((b * CDIM + c0 + ty) << 10) + p0 + tx];
    __syncthreads();
    g_zflat[(b * 1024 + p0 + ty) * CDIM + c0 + tx] = tile[tx][ty];
}

// ---------------------------------------------------------------------------
// 2) z_sq[t]
// ---------------------------------------------------------------------------
__global__ void k_zsq() {
    int t = blockIdx.x * 8 + threadIdx.y;
    int lane = threadIdx.x;
    float s = 0.f;
#pragma unroll
    for (int i = 0; i < 8; i++) {
        float v = g_zflat[t * CDIM + lane + i * 32];
        s += v * v;
    }
#pragma unroll
    for (int off = 16; off; off >>= 1) s += __shfl_down_sync(0xffffffffu, s, off);
    if (lane == 0) g_zsq[t] = s;
}

// ---------------------------------------------------------------------------
// 3) e_sq[k]
// ---------------------------------------------------------------------------
__global__ void k_esq(const float* __restrict__ cb) {
    int k = blockIdx.x * 8 + threadIdx.y;
    int lane = threadIdx.x;
    float s = 0.f;
#pragma unroll
    for (int i = 0; i < 8; i++) {
        float v = cb[k * CDIM + lane + i * 32];
        s += v * v;
    }
#pragma unroll
    for (int off = 16; off; off >>= 1) s += __shfl_down_sync(0xffffffffu, s, off);
    if (lane == 0) g_esq[k] = s;
}

// ---------------------------------------------------------------------------
// 4) fused GEMM (packed f32x2) + argmin.
//    Block: 64 tokens, 256 threads; thread tile 4 tokens x 8 codes.
//    z tile resident transposed zs[c][t]; codebook double-buffered in
//    BKT x BNT stages, staged through registers to hide L2 latency.
//    dist = fl(fl(z_sq - 2*cross) + e_sq) (matches reference elementwise)
// ---------------------------------------------------------------------------
__global__ void __launch_bounds__(256, 2) k_argmin(const float* __restrict__ cb,
                                                   float* __restrict__ out) {
    extern __shared__ float sm[];
    float* zs  = sm;                    // [256][ZS_S]  (c-major, token fastest)
    float* cbs = sm + CDIM * ZS_S;      // [2][BKT][CB_S]

    int t0  = blockIdx.x * BM;
    int tid = threadIdx.x;
    int tx  = tid & 15;                 // 16 code-columns (8 codes each)
    int ty  = tid >> 4;                 // 16 token-rows (4 tokens each)

    // load z tile, store transposed (one-time)
    for (int i = tid; i < BM * CDIM; i += 256) {
        int tk = i >> 8;
        int c  = i & 255;
        zs[c * ZS_S + tk] = g_zflat[(t0 + tk) * CDIM + c];
    }
    __syncthreads();

    float zsq[4];
#pragma unroll
    for (int u = 0; u < 4; u++) zsq[u] = g_zsq[t0 + ty * 4 + u];

    float bestd[4];
    int   besti[4];
#pragma unroll
    for (int u = 0; u < 4; u++) { bestd[u] = 3.4e38f; besti[u] = 0; }

    // codebook gmem staging: thread t loads row kk = t>>1, 8 channels at ch
    int kk = tid >> 1;
    int ch = (tid & 1) << 3;

    float4 s0, s1;                       // staged tile fragment
    const int NT = (KCB / BNT) * (CDIM / BKT);   // 64 * 16 = 1024 tiles

    // prologue: stage tile 0
    {
        const float* p = cb + kk * CDIM + ch;
        s0 = *reinterpret_cast<const float4*>(p);
        s1 = *reinterpret_cast<const float4*>(p + 4);
        float* q = cbs + ch * CB_S + kk;
        q[0 * CB_S] = s0.x; q[1 * CB_S] = s0.y; q[2 * CB_S] = s0.z; q[3 * CB_S] = s0.w;
        q[4 * CB_S] = s1.x; q[5 * CB_S] = s1.y; q[6 * CB_S] = s1.z; q[7 * CB_S] = s1.w;
    }
    __syncthreads();

    unsigned long long acc[4][4];
#pragma unroll
    for (int u = 0; u < 4; u++)
#pragma unroll
        for (int p = 0; p < 4; p++) acc[u][p] = 0ull;

    for (int kt = 0; kt < NT; kt++) {
        int buf = kt & 1;
        int c0  = (kt & 15) << 4;
        int k0  = (kt >> 4) << 7;

        // prefetch next tile into registers (latency hidden by compute)
        if (kt + 1 < NT) {
            int nk0 = ((kt + 1) >> 4) << 7;
            int nc0 = ((kt + 1) & 15) << 4;
            const float* p = cb + (nk0 + kk) * CDIM + nc0 + ch;
            s0 = *reinterpret_cast<const float4*>(p);
            s1 = *reinterpret_cast<const float4*>(p + 4);
        }

        const float* cbb = cbs + buf * (BKT * CB_S);
#pragma unroll
        for (int cc = 0; cc < BKT; cc++) {
            int c = c0 + cc;
            float4 av = *reinterpret_cast<const float4*>(&zs[c * ZS_S + ty * 4]);
            longlong2 b0 = *reinterpret_cast<const longlong2*>(&cbb[cc * CB_S + tx * 8]);
            longlong2 b1 = *reinterpret_cast<const longlong2*>(&cbb[cc * CB_S + tx * 8 + 4]);
            unsigned long long a0 = splat2(av.x);
            unsigned long long a1 = splat2(av.y);
            unsigned long long a2 = splat2(av.z);
            unsigned long long a3 = splat2(av.w);
            fma2(acc[0][0], a0, (unsigned long long)b0.x);
            fma2(acc[0][1], a0, (unsigned long long)b0.y);
            fma2(acc[0][2], a0, (unsigned long long)b1.x);
            fma2(acc[0][3], a0, (unsigned long long)b1.y);
            fma2(acc[1][0], a1, (unsigned long long)b0.x);
            fma2(acc[1][1], a1, (unsigned long long)b0.y);
            fma2(acc[1][2], a1, (unsigned long long)b1.x);
            fma2(acc[1][3], a1, (unsigned long long)b1.y);
            fma2(acc[2][0], a2, (unsigned long long)b0.x);
            fma2(acc[2][1], a2, (unsigned long long)b0.y);
            fma2(acc[2][2], a2, (unsigned long long)b1.x);
            fma2(acc[2][3], a2, (unsigned long long)b1.y);
            fma2(acc[3][0], a3, (unsigned long long)b0.x);
            fma2(acc[3][1], a3, (unsigned long long)b0.y);
            fma2(acc[3][2], a3, (unsigned long long)b1.x);
            fma2(acc[3][3], a3, (unsigned long long)b1.y);
        }

        // epilogue per 128-code tile: distances + running argmin
        if ((kt & 15) == 15) {
#pragma unroll
            for (int p = 0; p < 4; p++) {
                int   kl = k0 + tx * 8 + p * 2;
                float el = g_esq[kl];
                float eh = g_esq[kl + 1];
#pragma unroll
                for (int u = 0; u < 4; u++) {
                    float xl, xh;
                    unpack2(acc[u][p], xl, xh);
                    float dl = (zsq[u] - 2.0f * xl) + el;
                    float dh = (zsq[u] - 2.0f * xh) + eh;
                    if (dl < bestd[u] || (dl == bestd[u] && kl < besti[u])) {
                        bestd[u] = dl; besti[u] = kl;
                    }
                    if (dh < bestd[u] || (dh == bestd[u] && kl + 1 < besti[u])) {
                        bestd[u] = dh; besti[u] = kl + 1;
                    }
                    acc[u][p] = 0ull;
                }
            }
        }

        // publish next tile to the other smem buffer
        if (kt + 1 < NT) {
            __syncthreads();   // all warps done reading buf^1 (tile kt-1)
            float* q = cbs + (buf ^ 1) * (BKT * CB_S) + ch * CB_S + kk;
            q[0 * CB_S] = s0.x; q[1 * CB_S] = s0.y; q[2 * CB_S] = s0.z; q[3 * CB_S] = s0.w;
            q[4 * CB_S] = s1.x; q[5 * CB_S] = s1.y; q[6 * CB_S] = s1.z; q[7 * CB_S] = s1.w;
            __syncthreads();
        }
    }

    // reduce across the 16 tx lanes per token group
#pragma unroll
    for (int u = 0; u < 4; u++) {
        float d  = bestd[u];
        int   i_ = besti[u];
#pragma unroll
        for (int off = 8; off; off >>= 1) {
            float od = __shfl_down_sync(0xffffffffu, d, off, 16);
            int   oi = __shfl_down_sync(0xffffffffu, i_, off, 16);
            if (od < d || (od == d && oi < i_)) { d = od; i_ = oi; }
        }
        if (tx == 0) {
            int t = t0 + ty * 4 + u;
            g_codes[t] = i_;
            out[t]     = (float)i_;
        }
    }
}

// ---------------------------------------------------------------------------
// 5) gather quantized (NCHW) + per-token squared error
// ---------------------------------------------------------------------------
__global__ void k_quant(const float* __restrict__ cb, float* __restrict__ out) {
    int t = blockIdx.x;
    int c = threadIdx.x;
    int code = g_codes[t];
    float q  = cb[code * CDIM + c];
    float zv = g_zflat[t * CDIM + c];
    int b  = t >> 10;
    int hw = t & 1023;
    out[TOK + ((b * CDIM + c) << 10) + hw] = q;
    float dv  = q - zv;
    float dsq = dv * dv;

    __shared__ float red[256];
    red[c] = dsq;
    __syncthreads();
#pragma unroll
    for (int s = 128; s > 0; s >>= 1) {
        if (c < s) red[c] += red[c + s];
        __syncthreads();
    }
    if (c == 0) g_tokloss[t] = red[0];
}

// ---------------------------------------------------------------------------
// 6) final loss
// ---------------------------------------------------------------------------
__global__ void k_loss(float* __restrict__ out) {
    __shared__ float red[1024];
    int tid = threadIdx.x;
    float s = 0.f;
    for (int i = tid; i < TOK; i += 1024) s += g_tokloss[i];
    red[tid] = s;
    __syncthreads();
#pragma unroll
    for (int st = 512; st > 0; st >>= 1) {
        if (tid < st) red[tid] += red[tid + st];
        __syncthreads();
    }
    if (tid == 0)
        out[TOK + TOK * CDIM] = 1.25f * red[0] / (float)(TOK * CDIM);
}

// ---------------------------------------------------------------------------
extern "C" void kernel_launch(void* const* d_in, const int* in_sizes, int n_in,
                              void* d_out, int out_size) {
    const float* z  = (const float*)d_in[0];
    const float* cb = (const float*)d_in[1];
    float* out = (float*)d_out;

    k_transpose<<<dim3(32, 8, 16), dim3(32, 32)>>>(z);
    k_zsq<<<TOK / 8, dim3(32, 8)>>>();
    k_esq<<<KCB / 8, dim3(32, 8)>>>(cb);

    cudaFuncSetAttribute(k_argmin, cudaFuncAttributeMaxDynamicSharedMemorySize,
                         SMEM_BYTES);
    k_argmin<<<TOK / BM, 256, SMEM_BYTES>>>(cb, out);

    k_quant<<<TOK, 256>>>(cb, out);
    k_loss<<<1, 1024>>>(out);
}

// round 4
// speedup vs baseline: 1.5719x; 1.5719x over previous
#include <cuda_runtime.h>

#define TOK   16384
#define KCB   8192
#define CDIM  256
#define BM    64          // tokens per block
#define BN    128         // codes per k-tile
#define BK    32          // channels per smem stage

#define ZS_S  68          // zs[c][t] stride (floats)
#define CB_S  132         // cbs[c][k] stride (floats), rows 16B-aligned
#define SMEM_FLOATS (CDIM * ZS_S + BK * CB_S)
#define SMEM_BYTES  (SMEM_FLOATS * 4)

// scratch (device globals: no allocation allowed)
__device__ float g_zflat[TOK * CDIM];
__device__ float g_zsq[TOK];
__device__ float g_esq[KCB];
__device__ int   g_codes[TOK];
__device__ float g_tokloss[TOK];

typedef unsigned long long ull;

__device__ __forceinline__ ull splat2(float x) {
    ull r;
    asm("mov.b64 %0, {%1, %1};" : "=l"(r) : "r"(__float_as_uint(x)));
    return r;
}
__device__ __forceinline__ void fma2(ull& d, ull a, ull b) {
    asm("fma.rn.f32x2 %0, %1, %2, %0;" : "+l"(d) : "l"(a), "l"(b));
}
__device__ __forceinline__ void unpack2(ull v, float& lo, float& hi) {
    unsigned int l, h;
    asm("mov.b64 {%0, %1}, %2;" : "=r"(l), "=r"(h) : "l"(v));
    lo = __uint_as_float(l);
    hi = __uint_as_float(h);
}

// ---------------------------------------------------------------------------
// 1) transpose z (B,C,H,W) -> z_flat (t, c)
// ---------------------------------------------------------------------------
__global__ void k_transpose(const float* __restrict__ z) {
    __shared__ float tile[32][33];
    int b  = blockIdx.z;
    int c0 = blockIdx.y << 5;
    int p0 = blockIdx.x << 5;
    int tx = threadIdx.x, ty = threadIdx.y;
    tile[ty][tx] = z[((b * CDIM + c0 + ty) << 10) + p0 + tx];
    __syncthreads();
    g_zflat[(b * 1024 + p0 + ty) * CDIM + c0 + tx] = tile[tx][ty];
}

// ---------------------------------------------------------------------------
// 2) z_sq[t]
// ---------------------------------------------------------------------------
__global__ void k_zsq() {
    int t = blockIdx.x * 8 + threadIdx.y;
    int lane = threadIdx.x;
    float s = 0.f;
#pragma unroll
    for (int i = 0; i < 8; i++) {
        float v = g_zflat[t * CDIM + lane + i * 32];
        s += v * v;
    }
#pragma unroll
    for (int off = 16; off; off >>= 1) s += __shfl_down_sync(0xffffffffu, s, off);
    if (lane == 0) g_zsq[t] = s;
}

// ---------------------------------------------------------------------------
// 3) e_sq[k]
// ---------------------------------------------------------------------------
__global__ void k_esq(const float* __restrict__ cb) {
    int k = blockIdx.x * 8 + threadIdx.y;
    int lane = threadIdx.x;
    float s = 0.f;
#pragma unroll
    for (int i = 0; i < 8; i++) {
        float v = cb[k * CDIM + lane + i * 32];
        s += v * v;
    }
#pragma unroll
    for (int off = 16; off; off >>= 1) s += __shfl_down_sync(0xffffffffu, s, off);
    if (lane == 0) g_esq[k] = s;
}

// ---------------------------------------------------------------------------
// 4) fused GEMM (packed f32x2, conflict-free LDS) + argmin.
//    256 threads = 16 tx (code cols) x 16 ty (token rows).
//    Thread tile: 4 tokens x 8 codes, codes as pairs {2tx,2tx+1}+32p.
//    b-frag loads are LDS.64 with 8B lane stride -> all 32 banks, no conflict.
//    Stage prefetch: regs -> smem -> fire next LDG -> compute.
// ---------------------------------------------------------------------------
__global__ void __launch_bounds__(256, 2) k_argmin(const float* __restrict__ cb,
                                                   float* __restrict__ out) {
    extern __shared__ float sm[];
    float* zs  = sm;                    // [256][ZS_S]  c-major, token fastest
    float* cbs = sm + CDIM * ZS_S;      // [BK][CB_S]   single stage buffer

    int t0  = blockIdx.x * BM;
    int tid = threadIdx.x;
    int tx  = tid & 15;
    int ty  = tid >> 4;

    // one-time: z tile transposed into smem
    for (int i = tid; i < BM * CDIM; i += 256) {
        int tk = i >> 8;
        int c  = i & 255;
        zs[c * ZS_S + tk] = g_zflat[(t0 + tk) * CDIM + c];
    }

    float zsq[4];
#pragma unroll
    for (int u = 0; u < 4; u++) zsq[u] = g_zsq[t0 + ty * 4 + u];

    float bestd[4];
    int   besti[4];
#pragma unroll
    for (int u = 0; u < 4; u++) { bestd[u] = 3.4e38f; besti[u] = 0; }

    // staging map: linear float4 index idx4 = tid + j*256 over BN*BK floats
    //   kk = idx4>>3 (code row 0..127), cc4 = idx4&7 (channel group *4)
    int skk  = tid >> 3;          // base row for j=0 grows by 32 each j
    int scc4 = tid & 7;

    float4 s0, s1, s2, s3;

    // prologue: load stage (k0=0, c0=0) into regs
    {
        const float* p = cb + skk * CDIM + (scc4 << 2);
        s0 = *reinterpret_cast<const float4*>(p);
        s1 = *reinterpret_cast<const float4*>(p + 32 * CDIM);
        s2 = *reinterpret_cast<const float4*>(p + 64 * CDIM);
        s3 = *reinterpret_cast<const float4*>(p + 96 * CDIM);
    }

    const int NST = (KCB / BN) * (CDIM / BK);   // 64 * 8 = 512 stages

    for (int k0 = 0; k0 < KCB; k0 += BN) {
        ull acc[4][4];
#pragma unroll
        for (int u = 0; u < 4; u++)
#pragma unroll
            for (int p = 0; p < 4; p++) acc[u][p] = 0ull;

        for (int c0 = 0; c0 < CDIM; c0 += BK) {
            __syncthreads();   // everyone done reading previous stage
            // publish staged regs -> smem (transposed [cc][k])
            {
                float* q = cbs + (scc4 << 2) * CB_S + skk;
#pragma unroll
                for (int i = 0; i < 4; i++) {
                    float v0 = (i == 0) ? s0.x : (i == 1) ? s0.y : (i == 2) ? s0.z : s0.w;
                    float v1 = (i == 0) ? s1.x : (i == 1) ? s1.y : (i == 2) ? s1.z : s1.w;
                    float v2 = (i == 0) ? s2.x : (i == 1) ? s2.y : (i == 2) ? s2.z : s2.w;
                    float v3 = (i == 0) ? s3.x : (i == 1) ? s3.y : (i == 2) ? s3.z : s3.w;
                    q[i * CB_S +  0] = v0;
                    q[i * CB_S + 32] = v1;
                    q[i * CB_S + 64] = v2;
                    q[i * CB_S + 96] = v3;
                }
            }
            __syncthreads();

            // fire prefetch of next stage (fully latency-hidden by compute)
            int st = (k0 >> 7) * 8 + (c0 >> 5) + 1;
            if (st < NST) {
                int nk0 = (st >> 3) << 7;
                int nc0 = (st & 7) << 5;
                const float* p = cb + (nk0 + skk) * CDIM + nc0 + (scc4 << 2);
                s0 = *reinterpret_cast<const float4*>(p);
                s1 = *reinterpret_cast<const float4*>(p + 32 * CDIM);
                s2 = *reinterpret_cast<const float4*>(p + 64 * CDIM);
                s3 = *reinterpret_cast<const float4*>(p + 96 * CDIM);
            }

            // compute: 32 channels
#pragma unroll
            for (int cc = 0; cc < BK; cc++) {
                float4 av = *reinterpret_cast<const float4*>(
                    &zs[(c0 + cc) * ZS_S + ty * 4]);
                const float* row = cbs + cc * CB_S + tx * 2;
                ull b0 = *reinterpret_cast<const ull*>(row);
                ull b1 = *reinterpret_cast<const ull*>(row + 32);
                ull b2 = *reinterpret_cast<const ull*>(row + 64);
                ull b3 = *reinterpret_cast<const ull*>(row + 96);
                ull a0 = splat2(av.x);
                ull a1 = splat2(av.y);
                ull a2 = splat2(av.z);
                ull a3 = splat2(av.w);
                fma2(acc[0][0], a0, b0); fma2(acc[0][1], a0, b1);
                fma2(acc[0][2], a0, b2); fma2(acc[0][3], a0, b3);
                fma2(acc[1][0], a1, b0); fma2(acc[1][1], a1, b1);
                fma2(acc[1][2], a1, b2); fma2(acc[1][3], a1, b3);
                fma2(acc[2][0], a2, b0); fma2(acc[2][1], a2, b1);
                fma2(acc[2][2], a2, b2); fma2(acc[2][3], a2, b3);
                fma2(acc[3][0], a3, b0); fma2(acc[3][1], a3, b1);
                fma2(acc[3][2], a3, b2); fma2(acc[3][3], a3, b3);
            }
        }

        // epilogue: distances + running argmin (k = k0 + 2tx + 32p, then k+1)
#pragma unroll
        for (int p = 0; p < 4; p++) {
            int    kl = k0 + tx * 2 + p * 32;
            float2 ee = *reinterpret_cast<const float2*>(&g_esq[kl]);
#pragma unroll
            for (int u = 0; u < 4; u++) {
                float xl, xh;
                unpack2(acc[u][p], xl, xh);
                float dl = (zsq[u] - 2.0f * xl) + ee.x;
                float dh = (zsq[u] - 2.0f * xh) + ee.y;
                if (dl < bestd[u] || (dl == bestd[u] && kl < besti[u])) {
                    bestd[u] = dl; besti[u] = kl;
                }
                if (dh < bestd[u] || (dh == bestd[u] && kl + 1 < besti[u])) {
                    bestd[u] = dh; besti[u] = kl + 1;
                }
            }
        }
    }

    // reduce across the 16 tx lanes per token group
#pragma unroll
    for (int u = 0; u < 4; u++) {
        float d  = bestd[u];
        int   i_ = besti[u];
#pragma unroll
        for (int off = 8; off; off >>= 1) {
            float od = __shfl_down_sync(0xffffffffu, d, off, 16);
            int   oi = __shfl_down_sync(0xffffffffu, i_, off, 16);
            if (od < d || (od == d && oi < i_)) { d = od; i_ = oi; }
        }
        if (tx == 0) {
            int t = t0 + ty * 4 + u;
            g_codes[t] = i_;
            out[t]     = (float)i_;
        }
    }
}

// ---------------------------------------------------------------------------
// 5) gather quantized (NCHW) + per-token squared error
// ---------------------------------------------------------------------------
__global__ void k_quant(const float* __restrict__ cb, float* __restrict__ out) {
    int t = blockIdx.x;
    int c = threadIdx.x;
    int code = g_codes[t];
    float q  = cb[code * CDIM + c];
    float zv = g_zflat[t * CDIM + c];
    int b  = t >> 10;
    int hw = t & 1023;
    out[TOK + ((b * CDIM + c) << 10) + hw] = q;
    float dv  = q - zv;
    float dsq = dv * dv;

    __shared__ float red[256];
    red[c] = dsq;
    __syncthreads();
#pragma unroll
    for (int s = 128; s > 0; s >>= 1) {
        if (c < s) red[c] += red[c + s];
        __syncthreads();
    }
    if (c == 0) g_tokloss[t] = red[0];
}

// ---------------------------------------------------------------------------
// 6) final loss
// ---------------------------------------------------------------------------
__global__ void k_loss(float* __restrict__ out) {
    __shared__ float red[1024];
    int tid = threadIdx.x;
    float s = 0.f;
    for (int i = tid; i < TOK; i += 1024) s += g_tokloss[i];
    red[tid] = s;
    __syncthreads();
#pragma unroll
    for (int st = 512; st > 0; st >>= 1) {
        if (tid < st) red[tid] += red[tid + st];
        __syncthreads();
    }
    if (tid == 0)
        out[TOK + TOK * CDIM] = 1.25f * red[0] / (float)(TOK * CDIM);
}

// ---------------------------------------------------------------------------
extern "C" void kernel_launch(void* const* d_in, const int* in_sizes, int n_in,
                              void* d_out, int out_size) {
    const float* z  = (const float*)d_in[0];
    const float* cb = (const float*)d_in[1];
    float* out = (float*)d_out;

    k_transpose<<<dim3(32, 8, 16), dim3(32, 32)>>>(z);
    k_zsq<<<TOK / 8, dim3(32, 8)>>>();
    k_esq<<<KCB / 8, dim3(32, 8)>>>(cb);

    cudaFuncSetAttribute(k_argmin, cudaFuncAttributeMaxDynamicSharedMemorySize,
                         SMEM_BYTES);
    k_argmin<<<TOK / BM, 256, SMEM_BYTES>>>(cb, out);

    k_quant<<<TOK, 256>>>(cb, out);
    k_loss<<<1, 1024>>>(out);
}

// round 5
// speedup vs baseline: 1.5732x; 1.0008x over previous
#include <cuda_runtime.h>

#define TOK   16384
#define KCB   8192
#define CDIM  256
#define BM    64          // tokens per block
#define BN    128         // codes per k-tile
#define BK    32          // channels per smem stage

#define ZS_S  68          // zs[c][t] stride (floats)
#define CB_S  132         // cbs[c][k] stride (floats), rows 16B-aligned
#define SMEM_FLOATS (CDIM * ZS_S + BK * CB_S)
#define SMEM_BYTES  (SMEM_FLOATS * 4)

// scratch (device globals: no allocation allowed)
__device__ float g_zflat[TOK * CDIM];
__device__ float g_zsq[TOK];
__device__ float g_esq[KCB];
__device__ int   g_codes[TOK];
__device__ float g_tokloss[TOK];

typedef unsigned long long ull;

__device__ __forceinline__ ull splat2(float x) {
    ull r;
    asm("mov.b64 %0, {%1, %1};" : "=l"(r) : "r"(__float_as_uint(x)));
    return r;
}
__device__ __forceinline__ void fma2(ull& d, ull a, ull b) {
    asm("fma.rn.f32x2 %0, %1, %2, %0;" : "+l"(d) : "l"(a), "l"(b));
}
__device__ __forceinline__ void unpack2(ull v, float& lo, float& hi) {
    unsigned int l, h;
    asm("mov.b64 {%0, %1}, %2;" : "=r"(l), "=r"(h) : "l"(v));
    lo = __uint_as_float(l);
    hi = __uint_as_float(h);
}

// ---------------------------------------------------------------------------
// 1) transpose z (B,C,H,W) -> z_flat (t, c)
// ---------------------------------------------------------------------------
__global__ void k_transpose(const float* __restrict__ z) {
    __shared__ float tile[32][33];
    int b  = blockIdx.z;
    int c0 = blockIdx.y << 5;
    int p0 = blockIdx.x << 5;
    int tx = threadIdx.x, ty = threadIdx.y;
    tile[ty][tx] = z[((b * CDIM + c0 + ty) << 10) + p0 + tx];
    __syncthreads();
    g_zflat[(b * 1024 + p0 + ty) * CDIM + c0 + tx] = tile[tx][ty];
}

// ---------------------------------------------------------------------------
// 2) z_sq[t]
// ---------------------------------------------------------------------------
__global__ void k_zsq() {
    int t = blockIdx.x * 8 + threadIdx.y;
    int lane = threadIdx.x;
    float s = 0.f;
#pragma unroll
    for (int i = 0; i < 8; i++) {
        float v = g_zflat[t * CDIM + lane + i * 32];
        s += v * v;
    }
#pragma unroll
    for (int off = 16; off; off >>= 1) s += __shfl_down_sync(0xffffffffu, s, off);
    if (lane == 0) g_zsq[t] = s;
}

// ---------------------------------------------------------------------------
// 3) e_sq[k]
// ---------------------------------------------------------------------------
__global__ void k_esq(const float* __restrict__ cb) {
    int k = blockIdx.x * 8 + threadIdx.y;
    int lane = threadIdx.x;
    float s = 0.f;
#pragma unroll
    for (int i = 0; i < 8; i++) {
        float v = cb[k * CDIM + lane + i * 32];
        s += v * v;
    }
#pragma unroll
    for (int off = 16; off; off >>= 1) s += __shfl_down_sync(0xffffffffu, s, off);
    if (lane == 0) g_esq[k] = s;
}

// ---------------------------------------------------------------------------
// 4) fused GEMM (packed f32x2, conflict-free LDS) + argmin.
//    256 threads = 16 tx (code cols) x 16 ty (token rows).
//    Thread tile: 4 tokens x 8 codes, codes as pairs {2tx,2tx+1}+32p.
//    b-frag loads are LDS.64 with 8B lane stride -> all 32 banks, no conflict.
//    Stage prefetch: regs -> smem -> fire next LDG -> compute.
// ---------------------------------------------------------------------------
__global__ void __launch_bounds__(256, 2) k_argmin(const float* __restrict__ cb,
                                                   float* __restrict__ out) {
    extern __shared__ float sm[];
    float* zs  = sm;                    // [256][ZS_S]  c-major, token fastest
    float* cbs = sm + CDIM * ZS_S;      // [BK][CB_S]   single stage buffer

    int t0  = blockIdx.x * BM;
    int tid = threadIdx.x;
    int tx  = tid & 15;
    int ty  = tid >> 4;

    // one-time: z tile transposed into smem
    for (int i = tid; i < BM * CDIM; i += 256) {
        int tk = i >> 8;
        int c  = i & 255;
        zs[c * ZS_S + tk] = g_zflat[(t0 + tk) * CDIM + c];
    }

    float zsq[4];
#pragma unroll
    for (int u = 0; u < 4; u++) zsq[u] = g_zsq[t0 + ty * 4 + u];

    float bestd[4];
    int   besti[4];
#pragma unroll
    for (int u = 0; u < 4; u++) { bestd[u] = 3.4e38f; besti[u] = 0; }

    // staging map: linear float4 index idx4 = tid + j*256 over BN*BK floats
    //   kk = idx4>>3 (code row 0..127), cc4 = idx4&7 (channel group *4)
    int skk  = tid >> 3;          // base row for j=0 grows by 32 each j
    int scc4 = tid & 7;

    float4 s0, s1, s2, s3;

    // prologue: load stage (k0=0, c0=0) into regs
    {
        const float* p = cb + skk * CDIM + (scc4 << 2);
        s0 = *reinterpret_cast<const float4*>(p);
        s1 = *reinterpret_cast<const float4*>(p + 32 * CDIM);
        s2 = *reinterpret_cast<const float4*>(p + 64 * CDIM);
        s3 = *reinterpret_cast<const float4*>(p + 96 * CDIM);
    }

    const int NST = (KCB / BN) * (CDIM / BK);   // 64 * 8 = 512 stages

    for (int k0 = 0; k0 < KCB; k0 += BN) {
        ull acc[4][4];
#pragma unroll
        for (int u = 0; u < 4; u++)
#pragma unroll
            for (int p = 0; p < 4; p++) acc[u][p] = 0ull;

        for (int c0 = 0; c0 < CDIM; c0 += BK) {
            __syncthreads();   // everyone done reading previous stage
            // publish staged regs -> smem (transposed [cc][k])
            {
                float* q = cbs + (scc4 << 2) * CB_S + skk;
#pragma unroll
                for (int i = 0; i < 4; i++) {
                    float v0 = (i == 0) ? s0.x : (i == 1) ? s0.y : (i == 2) ? s0.z : s0.w;
                    float v1 = (i == 0) ? s1.x : (i == 1) ? s1.y : (i == 2) ? s1.z : s1.w;
                    float v2 = (i == 0) ? s2.x : (i == 1) ? s2.y : (i == 2) ? s2.z : s2.w;
                    float v3 = (i == 0) ? s3.x : (i == 1) ? s3.y : (i == 2) ? s3.z : s3.w;
                    q[i * CB_S +  0] = v0;
                    q[i * CB_S + 32] = v1;
                    q[i * CB_S + 64] = v2;
                    q[i * CB_S + 96] = v3;
                }
            }
            __syncthreads();

            // fire prefetch of next stage (fully latency-hidden by compute)
            int st = (k0 >> 7) * 8 + (c0 >> 5) + 1;
            if (st < NST) {
                int nk0 = (st >> 3) << 7;
                int nc0 = (st & 7) << 5;
                const float* p = cb + (nk0 + skk) * CDIM + nc0 + (scc4 << 2);
                s0 = *reinterpret_cast<const float4*>(p);
                s1 = *reinterpret_cast<const float4*>(p + 32 * CDIM);
                s2 = *reinterpret_cast<const float4*>(p + 64 * CDIM);
                s3 = *reinterpret_cast<const float4*>(p + 96 * CDIM);
            }

            // compute: 32 channels
#pragma unroll
            for (int cc = 0; cc < BK; cc++) {
                float4 av = *reinterpret_cast<const float4*>(
                    &zs[(c0 + cc) * ZS_S + ty * 4]);
                const float* row = cbs + cc * CB_S + tx * 2;
                ull b0 = *reinterpret_cast<const ull*>(row);
                ull b1 = *reinterpret_cast<const ull*>(row + 32);
                ull b2 = *reinterpret_cast<const ull*>(row + 64);
                ull b3 = *reinterpret_cast<const ull*>(row + 96);
                ull a0 = splat2(av.x);
                ull a1 = splat2(av.y);
                ull a2 = splat2(av.z);
                ull a3 = splat2(av.w);
                fma2(acc[0][0], a0, b0); fma2(acc[0][1], a0, b1);
                fma2(acc[0][2], a0, b2); fma2(acc[0][3], a0, b3);
                fma2(acc[1][0], a1, b0); fma2(acc[1][1], a1, b1);
                fma2(acc[1][2], a1, b2); fma2(acc[1][3], a1, b3);
                fma2(acc[2][0], a2, b0); fma2(acc[2][1], a2, b1);
                fma2(acc[2][2], a2, b2); fma2(acc[2][3], a2, b3);
                fma2(acc[3][0], a3, b0); fma2(acc[3][1], a3, b1);
                fma2(acc[3][2], a3, b2); fma2(acc[3][3], a3, b3);
            }
        }

        // epilogue: distances + running argmin (k = k0 + 2tx + 32p, then k+1)
#pragma unroll
        for (int p = 0; p < 4; p++) {
            int    kl = k0 + tx * 2 + p * 32;
            float2 ee = *reinterpret_cast<const float2*>(&g_esq[kl]);
#pragma unroll
            for (int u = 0; u < 4; u++) {
                float xl, xh;
                unpack2(acc[u][p], xl, xh);
                float dl = (zsq[u] - 2.0f * xl) + ee.x;
                float dh = (zsq[u] - 2.0f * xh) + ee.y;
                if (dl < bestd[u] || (dl == bestd[u] && kl < besti[u])) {
                    bestd[u] = dl; besti[u] = kl;
                }
                if (dh < bestd[u] || (dh == bestd[u] && kl + 1 < besti[u])) {
                    bestd[u] = dh; besti[u] = kl + 1;
                }
            }
        }
    }

    // reduce across the 16 tx lanes per token group
#pragma unroll
    for (int u = 0; u < 4; u++) {
        float d  = bestd[u];
        int   i_ = besti[u];
#pragma unroll
        for (int off = 8; off; off >>= 1) {
            float od = __shfl_down_sync(0xffffffffu, d, off, 16);
            int   oi = __shfl_down_sync(0xffffffffu, i_, off, 16);
            if (od < d || (od == d && oi < i_)) { d = od; i_ = oi; }
        }
        if (tx == 0) {
            int t = t0 + ty * 4 + u;
            g_codes[t] = i_;
            out[t]     = (float)i_;
        }
    }
}

// ---------------------------------------------------------------------------
// 5) gather quantized (NCHW) + per-token squared error
// ---------------------------------------------------------------------------
__global__ void k_quant(const float* __restrict__ cb, float* __restrict__ out) {
    int t = blockIdx.x;
    int c = threadIdx.x;
    int code = g_codes[t];
    float q  = cb[code * CDIM + c];
    float zv = g_zflat[t * CDIM + c];
    int b  = t >> 10;
    int hw = t & 1023;
    out[TOK + ((b * CDIM + c) << 10) + hw] = q;
    float dv  = q - zv;
    float dsq = dv * dv;

    __shared__ float red[256];
    red[c] = dsq;
    __syncthreads();
#pragma unroll
    for (int s = 128; s > 0; s >>= 1) {
        if (c < s) red[c] += red[c + s];
        __syncthreads();
    }
    if (c == 0) g_tokloss[t] = red[0];
}

// ---------------------------------------------------------------------------
// 6) final loss
// ---------------------------------------------------------------------------
__global__ void k_loss(float* __restrict__ out) {
    __shared__ float red[1024];
    int tid = threadIdx.x;
    float s = 0.f;
    for (int i = tid; i < TOK; i += 1024) s += g_tokloss[i];
    red[tid] = s;
    __syncthreads();
#pragma unroll
    for (int st = 512; st > 0; st >>= 1) {
        if (tid < st) red[tid] += red[tid + st];
        __syncthreads();
    }
    if (tid == 0)
        out[TOK + TOK * CDIM] = 1.25f * red[0] / (float)(TOK * CDIM);
}

// ---------------------------------------------------------------------------
extern "C" void kernel_launch(void* const* d_in, const int* in_sizes, int n_in,
                              void* d_out, int out_size) {
    const float* z  = (const float*)d_in[0];
    const float* cb = (const float*)d_in[1];
    float* out = (float*)d_out;

    k_transpose<<<dim3(32, 8, 16), dim3(32, 32)>>>(z);
    k_zsq<<<TOK / 8, dim3(32, 8)>>>();
    k_esq<<<KCB / 8, dim3(32, 8)>>>(cb);

    cudaFuncSetAttribute(k_argmin, cudaFuncAttributeMaxDynamicSharedMemorySize,
                         SMEM_BYTES);
    k_argmin<<<TOK / BM, 256, SMEM_BYTES>>>(cb, out);

    k_quant<<<TOK, 256>>>(cb, out);
    k_loss<<<1, 1024>>>(out);
}